// round 15
// baseline (speedup 1.0000x reference)
#include <cuda_runtime.h>
#include <cuda_bf16.h>
#include <math.h>

#define NN    512
#define EPN   511
#define FD    128
#define TILE  64
#define NTILE 8
#define NTHR  256

__device__ float g_vec0[NN * 3];
__device__ float g_vec [NN * 3];
__device__ float g_hf  [NN * FD];
__device__ float g_hs  [NN * FD];
__device__ float g_hr  [NN * FD];
__device__ float g_magg[NN * FD];
__device__ float g_vac [NN * 3];
// 6 matrices (2 blocks x {We1, Wc=We2@Wx0, Wx1}) as T[n][k] images, 64KB each: [hi|lo]
__device__ __align__(16) __nv_bfloat16 g_wb[6 * 32768];
// per block: [0..127] we2winf, [128..255] bc, [256] binf'
__device__ float g_aux[2 * 257];

__device__ __forceinline__ float siluf(float x) {
    return __fdividef(x, 1.f + __expf(-x));
}
__device__ __forceinline__ float sigmf(float x) {
    return __fdividef(1.f, 1.f + __expf(-x));
}

__device__ __forceinline__ unsigned smem_u32(const void* p) {
    unsigned a;
    asm("{ .reg .u64 t; cvta.to.shared.u64 t, %1; cvt.u32.u64 %0, t; }" : "=r"(a) : "l"(p));
    return a;
}
__device__ __forceinline__ void cpasync16(unsigned d, const void* g) {
    asm volatile("cp.async.cg.shared.global [%0], [%1], 16;" :: "r"(d), "l"(g));
}
#define CP_COMMIT() asm volatile("cp.async.commit_group;" ::: "memory")
#define CP_WAIT0()  asm volatile("cp.async.wait_group 0;"  ::: "memory")
#define BAR_PAIR(id) asm volatile("bar.sync %0, 64;" :: "r"(id) : "memory")

__device__ __forceinline__ void ldsm4(unsigned* r, unsigned a) {
    asm volatile("ldmatrix.sync.aligned.m8n8.x4.shared.b16 {%0,%1,%2,%3}, [%4];"
        : "=r"(r[0]), "=r"(r[1]), "=r"(r[2]), "=r"(r[3]) : "r"(a));
}
__device__ __forceinline__ void mma16816(float* c, const unsigned* a,
                                         unsigned b0, unsigned b1) {
    asm volatile("mma.sync.aligned.m16n8k16.row.col.f32.bf16.bf16.f32 "
        "{%0,%1,%2,%3}, {%4,%5,%6,%7}, {%8,%9}, {%0,%1,%2,%3};"
        : "+f"(c[0]), "+f"(c[1]), "+f"(c[2]), "+f"(c[3])
        : "r"(a[0]), "r"(a[1]), "r"(a[2]), "r"(a[3]), "r"(b0), "r"(b1));
}

// image layout: row-major [row][k], 256B rows, 16B chunks XOR-swizzled by row&7
__device__ __forceinline__ int img_off(int e, int c) {
    return (e << 8) + ((((c >> 3) ^ (e & 7))) << 4) + ((c & 7) << 1);
}
__device__ __forceinline__ void st_split2(char* hb, char* lb, int off,
                                          float v0, float v1) {
    __nv_bfloat16 h0 = __float2bfloat16(v0), h1 = __float2bfloat16(v1);
    __nv_bfloat16 l0 = __float2bfloat16(v0 - __bfloat162float(h0));
    __nv_bfloat16 l1 = __float2bfloat16(v1 - __bfloat162float(h1));
    *reinterpret_cast<unsigned*>(hb + off) =
        (unsigned)__bfloat16_as_ushort(h0) | ((unsigned)__bfloat16_as_ushort(h1) << 16);
    *reinterpret_cast<unsigned*>(lb + off) =
        (unsigned)__bfloat16_as_ushort(l0) | ((unsigned)__bfloat16_as_ushort(l1) << 16);
}

struct __align__(16) ES {
    char xhi[16384]; char xlo[16384];   // act0 / Y2 images [e][k], 64 rows
    char yhi[16384]; char ylo[16384];   // G1 output images
    char bbuf[32768];                   // weight term; 4 x 8KB pair regions
    float dv[3 * TILE], len[TILE], l2[TILE], gate[TILE], pxs[TILE];
    float gpart[4 * TILE];
    float w0[FD], hrb[FD], winf[FD], wxo[FD];
    float bb1[FD], bb2[FD], bbx1[FD];
    float maggs[2 * FD], vred[3 * TILE], vaccs[4], rvec[3];
    int   sidx[TILE];
};

// pair (64 threads, pl=0..63) loads its 8KB region: rows [32g, 32g+32) of one term
__device__ __forceinline__ void loadBpair(char* dstreg, const __nv_bfloat16* srcreg,
                                          int pl) {
    unsigned sd = smem_u32(dstreg);
    const float4* s4 = reinterpret_cast<const float4*>(srcreg);
#pragma unroll
    for (int q = 0; q < 8; q++) { int u = pl + q * 64; cpasync16(sd + u * 16, s4 + u); }
    CP_COMMIT();
}

// C[64e][128c] = split3( A @ W ); 8 warps, each a 32e x 32c tile.
// Weight staging PAIR-SCOPED. FOLD (G1 only): computes gate from the DOT
// partials, then ys += gate*silu(acc+bias) and gs += gate from live regs.
template <bool ACT, bool DOT, bool STORE, bool FOLD = false>
__device__ __forceinline__ void gemm_tc(ES* S, const char* Ahi, const char* Alo,
                                        const __nv_bfloat16* wcur,
                                        const __nv_bfloat16* wnext,
                                        const float* bias, const float* dw,
                                        char* Ohi, char* Olo, int t,
                                        float binf_s = 0.f, int tile = 0)
{
    const int w = t >> 5, lane = t & 31;
    const int g = w & 3;
    const int e0 = (w >> 2) * 32, c0 = g * 32;
    const int pl = ((w >> 2) << 5) | lane;
    char* breg = S->bbuf + g * 8192;
    const unsigned l7 = lane & 7;
    float acc[2][4][4];
#pragma unroll
    for (int mt = 0; mt < 2; mt++)
#pragma unroll
        for (int nt = 0; nt < 4; nt++)
#pragma unroll
            for (int q = 0; q < 4; q++) acc[mt][nt][q] = 0.f;

    const unsigned arow = e0 + (lane & 15);
    const unsigned acb  = lane >> 4;
    const unsigned browl = ((lane >> 4) << 3) + l7;
    const unsigned bcb  = (lane >> 3) & 1;
    const unsigned abh = smem_u32(Ahi) + arow * 256;
    const unsigned abl = smem_u32(Alo) + arow * 256;
    const unsigned bb  = smem_u32(breg) + browl * 256;

    CP_WAIT0();                      // W_hi region (issued by prev gemm) arrived
    BAR_PAIR(g + 1);

    // ---- pass 1: B = W_hi; hi-MMAs then lo-MMAs ----
#pragma unroll
    for (int ks = 0; ks < 8; ks++) {
        unsigned ach = (((unsigned)(ks << 1)) | acb) ^ l7;
        unsigned bch = (((unsigned)(ks << 1)) | bcb) ^ l7;
        unsigned ah0[4], ah1[4], al0[4], al1[4], b0[4], b1[4];
        ldsm4(ah0, abh + (ach << 4));
        ldsm4(ah1, abh + 16 * 256 + (ach << 4));
        ldsm4(al0, abl + (ach << 4));
        ldsm4(al1, abl + 16 * 256 + (ach << 4));
        ldsm4(b0, bb + (bch << 4));
        ldsm4(b1, bb + 16 * 256 + (bch << 4));
        mma16816(acc[0][0], ah0, b0[0], b0[1]); mma16816(acc[0][1], ah0, b0[2], b0[3]);
        mma16816(acc[1][0], ah1, b0[0], b0[1]); mma16816(acc[1][1], ah1, b0[2], b0[3]);
        mma16816(acc[0][2], ah0, b1[0], b1[1]); mma16816(acc[0][3], ah0, b1[2], b1[3]);
        mma16816(acc[1][2], ah1, b1[0], b1[1]); mma16816(acc[1][3], ah1, b1[2], b1[3]);
        mma16816(acc[0][0], al0, b0[0], b0[1]); mma16816(acc[0][1], al0, b0[2], b0[3]);
        mma16816(acc[1][0], al1, b0[0], b0[1]); mma16816(acc[1][1], al1, b0[2], b0[3]);
        mma16816(acc[0][2], al0, b1[0], b1[1]); mma16816(acc[0][3], al0, b1[2], b1[3]);
        mma16816(acc[1][2], al1, b1[0], b1[1]); mma16816(acc[1][3], al1, b1[2], b1[3]);
    }
    BAR_PAIR(g + 1);                               // pair done reading W_hi
    loadBpair(breg, wcur + 16384 + g * 4096, pl);  // swap in W_lo region
    CP_WAIT0();
    BAR_PAIR(g + 1);

    // ---- pass 2: B = W_lo; A = hi only ----
#pragma unroll
    for (int ks = 0; ks < 8; ks++) {
        unsigned ach = (((unsigned)(ks << 1)) | acb) ^ l7;
        unsigned bch = (((unsigned)(ks << 1)) | bcb) ^ l7;
        unsigned ah0[4], ah1[4];
        ldsm4(ah0, abh + (ach << 4));
        ldsm4(ah1, abh + 16 * 256 + (ach << 4));
#pragma unroll
        for (int p = 0; p < 2; p++) {
            unsigned b[4];
            ldsm4(b, bb + p * 16 * 256 + (bch << 4));
            mma16816(acc[0][2 * p],     ah0, b[0], b[1]);
            mma16816(acc[0][2 * p + 1], ah0, b[2], b[3]);
            mma16816(acc[1][2 * p],     ah1, b[0], b[1]);
            mma16816(acc[1][2 * p + 1], ah1, b[2], b[3]);
        }
    }
    BAR_PAIR(g + 1);                         // pair done reading W_lo
    loadBpair(breg, wnext + g * 4096, pl);   // prefetch next matrix W_hi region

    const int r = lane >> 2, n2 = (lane & 3) * 2;
    float drow[2][2] = {{0.f, 0.f}, {0.f, 0.f}};
#pragma unroll
    for (int mt = 0; mt < 2; mt++) {
        int eA = e0 + mt * 16 + r;
#pragma unroll
        for (int nt = 0; nt < 4; nt++) {
            int c = c0 + nt * 8 + n2;
            float b0v = bias[c], b1v = bias[c + 1];
            float v00 = acc[mt][nt][0] + b0v, v01 = acc[mt][nt][1] + b1v;
            float v10 = acc[mt][nt][2] + b0v, v11 = acc[mt][nt][3] + b1v;
            if (ACT) { v00 = siluf(v00); v01 = siluf(v01);
                       v10 = siluf(v10); v11 = siluf(v11); }
            if (DOT) {
                drow[mt][0] += v00 * dw[c] + v01 * dw[c + 1];
                drow[mt][1] += v10 * dw[c] + v11 * dw[c + 1];
            }
            if (STORE) {
                st_split2(Ohi, Olo, img_off(eA, c), v00, v01);
                st_split2(Ohi, Olo, img_off(eA + 8, c), v10, v11);
            }
        }
    }
    if (DOT) {
#pragma unroll
        for (int mt = 0; mt < 2; mt++)
#pragma unroll
            for (int hb = 0; hb < 2; hb++) {
                float v = drow[mt][hb];
                v += __shfl_xor_sync(0xffffffffu, v, 1);
                v += __shfl_xor_sync(0xffffffffu, v, 2);
                if ((lane & 3) == 0)
                    S->gpart[g * TILE + e0 + mt * 16 + hb * 8 + r] = v;
            }
    }

    if (FOLD) {
        __syncthreads();                      // gpart complete across warps
        if (t < TILE) {
            bool valid = (tile * TILE + t) < EPN;
            S->gate[t] = valid ? sigmf(binf_s + S->gpart[t] + S->gpart[TILE + t]
                                       + S->gpart[2 * TILE + t] + S->gpart[3 * TILE + t])
                               : 0.f;
        }
        __syncthreads();                      // gate visible
        if (t < 32) {                         // gs += sum(gate)
            float v = S->gate[t] + S->gate[t + 32];
#pragma unroll
            for (int o = 16; o; o >>= 1) v += __shfl_down_sync(0xffffffffu, v, o);
            if (t == 0) S->vaccs[3] += v;
        }
        // ys fold from live acc: ys[c] += sum_e gate[e]*silu(acc+bias)
        float mc[4][2];
#pragma unroll
        for (int nt = 0; nt < 4; nt++) { mc[nt][0] = 0.f; mc[nt][1] = 0.f; }
#pragma unroll
        for (int mt = 0; mt < 2; mt++) {
            float gA = S->gate[e0 + mt * 16 + r];
            float gB = S->gate[e0 + mt * 16 + 8 + r];
#pragma unroll
            for (int nt = 0; nt < 4; nt++) {
                int c = c0 + nt * 8 + n2;
                float b0v = bias[c], b1v = bias[c + 1];
                mc[nt][0] += gA * siluf(acc[mt][nt][0] + b0v)
                           + gB * siluf(acc[mt][nt][2] + b0v);
                mc[nt][1] += gA * siluf(acc[mt][nt][1] + b1v)
                           + gB * siluf(acc[mt][nt][3] + b1v);
            }
        }
#pragma unroll
        for (int nt = 0; nt < 4; nt++)
#pragma unroll
            for (int j = 0; j < 2; j++) {
                float v = mc[nt][j];
                v += __shfl_xor_sync(0xffffffffu, v, 4);
                v += __shfl_xor_sync(0xffffffffu, v, 8);
                v += __shfl_xor_sync(0xffffffffu, v, 16);
                mc[nt][j] = v;
            }
        if (lane < 4) {
            int eg = w >> 2;
#pragma unroll
            for (int nt = 0; nt < 4; nt++)
#pragma unroll
                for (int j = 0; j < 2; j++) {
                    int c = c0 + nt * 8 + lane * 2 + j;
                    S->maggs[eg * FD + c] += mc[nt][j];
                }
        }
    }
}

__global__ void __launch_bounds__(NTHR, 2)
kedge(const int* __restrict__ senders, const float* __restrict__ We0r0,
      const float* __restrict__ be1, const float* __restrict__ bx1,
      const float* __restrict__ Wxo, const float* __restrict__ bxop,
      const float* __restrict__ We2g, const float* __restrict__ be2g, int blk)
{
    extern __shared__ char smraw[];
    ES* S = reinterpret_cast<ES*>(smraw);
    const int t = threadIdx.x, i = blockIdx.x;
    const int w = t >> 5, lane = t & 31;
    const int g = w & 3;
    const int pl = ((w >> 2) << 5) | lane;
    const __nv_bfloat16* wb = g_wb + blk * 3 * 32768;
    const float* aux = g_aux + blk * 257;

    if (t < FD) {
        S->w0[t] = We0r0[t]; S->hrb[t] = g_hr[i * FD + t];
        S->winf[t] = aux[t];            // we2winf
        S->bb2[t] = aux[FD + t];        // bc
        S->wxo[t] = Wxo[t];
        S->bb1[t] = be1[t]; S->bbx1[t] = bx1[t];
    }
    S->maggs[t] = 0.f;
    if (t < 4) S->vaccs[t] = 0.f;
    if (t < 3) S->rvec[t] = g_vec[i * 3 + t];
    const float binf_s = aux[256], bxo_s = bxop[0];

    loadBpair(S->bbuf + g * 8192, wb + g * 4096, pl);   // We1 hi, pair region
    __syncthreads();

    for (int tile = 0; tile < NTILE; tile++) {
        if (t < TILE) {                                  // stage 1
            int je = tile * TILE + t;
            bool valid = je < EPN;
            int s = valid ? senders[i * EPN + je] : i;
            S->sidx[t] = s;
            float d0 = 0.f, d1 = 0.f, d2 = 0.f;
            if (valid) {
                d0 = S->rvec[0] - g_vec[s * 3 + 0];
                d1 = S->rvec[1] - g_vec[s * 3 + 1];
                d2 = S->rvec[2] - g_vec[s * 3 + 2];
            }
            S->dv[t * 3] = d0; S->dv[t * 3 + 1] = d1; S->dv[t * 3 + 2] = d2;
            float dot = d0 * d0 + d1 * d1 + d2 * d2 + 1e-20f;
            S->l2[t] = valid ? dot : 0.f;
            S->len[t] = sqrtf(dot);
        }
        __syncthreads();
        {                                                // stage 2: act0 -> X
            int e = t >> 2, kh = t & 3;
            int s = S->sidx[e];
            float l2v = S->l2[e];
            const float* hsr = g_hs + s * FD + kh * 32;
#pragma unroll 8
            for (int j = 0; j < 32; j += 2) {
                int c = kh * 32 + j;
                float v0 = siluf(l2v * S->w0[c]     + hsr[j]     + S->hrb[c]);
                float v1 = siluf(l2v * S->w0[c + 1] + hsr[j + 1] + S->hrb[c + 1]);
                st_split2(S->xhi, S->xlo, img_off(e, c), v0, v1);
            }
        }
        __syncthreads();

        // G1: Y = silu(X @ We1 + be1); gate dot (we2winf) + ys/gs fold
        gemm_tc<true, true, true, true>(S, S->xhi, S->xlo,
                                   wb + 0 * 32768, wb + 1 * 32768,
                                   S->bb1, S->winf, S->yhi, S->ylo, t,
                                   binf_s, tile);
        __syncthreads();

        // G3': Y2 = silu(Y @ Wc + bc)   (Wc = We2@Wx0 precomputed)
        gemm_tc<true, false, true>(S, S->yhi, S->ylo,
                                   wb + 1 * 32768, wb + 2 * 32768,
                                   S->bb2, 0, S->xhi, S->xlo, t);
        __syncthreads();

        // G4: px partial = silu(Y2 @ Wx1 + bx1) . wxo  (no store); next = We1
        gemm_tc<true, true, false>(S, S->xhi, S->xlo,
                                   wb + 2 * 32768, wb + 0 * 32768,
                                   S->bbx1, S->wxo, S->yhi, S->ylo, t);
        __syncthreads();
        if (t < TILE)
            S->pxs[t] = __fdividef(bxo_s + S->gpart[t] + S->gpart[TILE + t]
                                   + S->gpart[2 * TILE + t] + S->gpart[3 * TILE + t],
                                   1.f + S->len[t]);
        __syncthreads();
        if (t < TILE) {                                  // vac partial
            float p = S->pxs[t];
            S->vred[t] = p * S->dv[t * 3];
            S->vred[TILE + t] = p * S->dv[t * 3 + 1];
            S->vred[2 * TILE + t] = p * S->dv[t * 3 + 2];
        }
        __syncthreads();
        if (t < 96) {
            int c = t >> 5, l = t & 31;
            const float* vr = S->vred + c * TILE;
            float v = vr[l] + vr[l + 32];
#pragma unroll
            for (int o = 16; o; o >>= 1) v += __shfl_down_sync(0xffffffffu, v, o);
            if (l == 0) S->vaccs[c] += v;
        }
        __syncthreads();
    }

    // writeout: magg = (ys @ We2) + gs*be2, scaled
    if (t < FD) S->gpart[t] = S->maggs[t] + S->maggs[FD + t];   // ys
    __syncthreads();
    if (t < FD) {
        float a = S->vaccs[3] * be2g[t];
#pragma unroll 8
        for (int k = 0; k < FD; k++) a += S->gpart[k] * We2g[k * FD + t];
        g_magg[i * FD + t] = a * rsqrtf(511.f);
    }
    if (t < 3) g_vac[i * 3 + t] = S->vaccs[t] * (1.f / 511.f);
}

// weights -> T[n][k] bf16 hi/lo swizzled images.
// grid 6: m = b*3+g; g0: We1 copy, g1: Wc = We2@Wx0 (computed) + aux, g2: Wx1 copy
__global__ void __launch_bounds__(256) kwprep(
    const float* __restrict__ We1, const float* __restrict__ We2,
    const float* __restrict__ Wx0, const float* __restrict__ Wx1,
    const float* __restrict__ Winf, const float* __restrict__ be2,
    const float* __restrict__ bx0, const float* __restrict__ binf)
{
    extern __shared__ float sW[];          // 64KB: Wx0 block (fp32)
    int m = blockIdx.x, b = m / 3, g = m % 3;
    int t = threadIdx.x;
    char* blob = reinterpret_cast<char*>(g_wb + m * 32768);

    if (g == 1) {
        const float* We2g = We2 + b * FD * FD;
        const float* Wx0g = Wx0 + b * FD * FD;
        const float* winfg = Winf + b * FD;
        const float* be2g = be2 + b * FD;
        const float* bx0g = bx0 + b * FD;
        float* aux = g_aux + b * 257;
        for (int idx = t; idx < FD * FD; idx += 256) sW[idx] = Wx0g[idx];
        __syncthreads();
        for (int ii = 0; ii < 64; ii++) {
            int idx = t + ii * 256;
            int k = idx >> 7, n = idx & 127;
            float a = 0.f;
#pragma unroll 8
            for (int j = 0; j < FD; j++) a += We2g[k * FD + j] * sW[j * FD + n];
            __nv_bfloat16 h = __float2bfloat16(a);
            __nv_bfloat16 l = __float2bfloat16(a - __bfloat162float(h));
            int off = (n << 8) + ((((k >> 3) ^ (n & 7))) << 4) + ((k & 7) << 1);
            *reinterpret_cast<__nv_bfloat16*>(blob + off) = h;
            *reinterpret_cast<__nv_bfloat16*>(blob + 32768 + off) = l;
        }
        if (t < FD) {
            float a = 0.f;
#pragma unroll 8
            for (int c = 0; c < FD; c++) a += We2g[t * FD + c] * winfg[c];
            aux[t] = a;                       // we2winf
            float bcv = bx0g[t];
#pragma unroll 8
            for (int j = 0; j < FD; j++) bcv += be2g[j] * sW[j * FD + t];
            aux[FD + t] = bcv;                // bc
        }
        if (t == 0) {
            float a = binf[b];
#pragma unroll 8
            for (int c = 0; c < FD; c++) a += be2g[c] * winfg[c];
            aux[256] = a;                     // binf'
        }
        return;
    }

    const float* W = (g == 0 ? We1 : Wx1) + b * FD * FD;
    int n = t & 127, kh = t >> 7;
    for (int kc = 0; kc < 8; kc++) {
        int kchunk = kh * 8 + kc;
        unsigned qh[4], ql[4];
#pragma unroll
        for (int u = 0; u < 4; u++) {
            int k = kchunk * 8 + u * 2;
            float x0 = W[k * FD + n], x1 = W[(k + 1) * FD + n];
            __nv_bfloat16 h0 = __float2bfloat16(x0), h1 = __float2bfloat16(x1);
            __nv_bfloat16 l0 = __float2bfloat16(x0 - __bfloat162float(h0));
            __nv_bfloat16 l1 = __float2bfloat16(x1 - __bfloat162float(h1));
            qh[u] = (unsigned)__bfloat16_as_ushort(h0) | ((unsigned)__bfloat16_as_ushort(h1) << 16);
            ql[u] = (unsigned)__bfloat16_as_ushort(l0) | ((unsigned)__bfloat16_as_ushort(l1) << 16);
        }
        int off = (n << 8) + ((kchunk ^ (n & 7)) << 4);
        *reinterpret_cast<uint4*>(blob + off)         = make_uint4(qh[0], qh[1], qh[2], qh[3]);
        *reinterpret_cast<uint4*>(blob + 32768 + off) = make_uint4(ql[0], ql[1], ql[2], ql[3]);
    }
}

__global__ void ksetup(const float* __restrict__ x)
{
    __shared__ float r0[256], r1[256], r2[256];
    __shared__ float mean[3];
    int t = threadIdx.x;
    float s0 = 0.f, s1 = 0.f, s2 = 0.f;
    for (int n = t; n < NN; n += 256) {
        s0 += x[n * 3]; s1 += x[n * 3 + 1]; s2 += x[n * 3 + 2];
    }
    r0[t] = s0; r1[t] = s1; r2[t] = s2;
    __syncthreads();
    for (int s = 128; s > 0; s >>= 1) {
        if (t < s) { r0[t] += r0[t + s]; r1[t] += r1[t + s]; r2[t] += r2[t + s]; }
        __syncthreads();
    }
    if (t == 0) { mean[0] = r0[0] / NN; mean[1] = r1[0] / NN; mean[2] = r2[0] / NN; }
    __syncthreads();
    for (int n = t; n < NN; n += 256)
#pragma unroll
        for (int c = 0; c < 3; c++) {
            float v = x[n * 3 + c] - mean[c];
            g_vec[n * 3 + c] = v; g_vec0[n * 3 + c] = v;
        }
}

__global__ void knode0(const float* __restrict__ h,
                       const float* __restrict__ Wh0, const float* __restrict__ bh0,
                       const float* __restrict__ We0, const float* __restrict__ be0)
{
    __shared__ float hrow[16];
    __shared__ float hfs[FD];
    int i = blockIdx.x, c = threadIdx.x;
    if (c < 16) hrow[c] = h[i * 16 + c];
    __syncthreads();
    float acc = bh0[c];
#pragma unroll
    for (int k = 0; k < 16; k++) acc += hrow[k] * Wh0[k * FD + c];
    g_hf[i * FD + c] = acc;
    hfs[c] = acc;
    __syncthreads();
    float s1 = 0.f, s2 = be0[c];
#pragma unroll 8
    for (int k = 0; k < FD; k++) {
        float hv = hfs[k];
        s1 += hv * We0[(1 + k) * FD + c];
        s2 += hv * We0[(129 + k) * FD + c];
    }
    g_hs[i * FD + c] = s1;
    g_hr[i * FD + c] = s2;
}

__global__ void knode(const float* __restrict__ Wp0, const float* __restrict__ bp0,
                      const float* __restrict__ Wp1, const float* __restrict__ bp1,
                      const float* __restrict__ Wpl, const float* __restrict__ bpl,
                      const float* __restrict__ We0n, const float* __restrict__ be0n,
                      int doNext)
{
    __shared__ float in0[2 * FD], t0s[FD], t1s[FD];
    int i = blockIdx.x, c = threadIdx.x;
    if (c < 3) g_vec[i * 3 + c] += g_vac[i * 3 + c];
    in0[c] = g_magg[i * FD + c];
    float hf = g_hf[i * FD + c];
    in0[FD + c] = hf;
    __syncthreads();
    float a = bp0[c];
#pragma unroll 8
    for (int k = 0; k < 2 * FD; k++) a += in0[k] * Wp0[k * FD + c];
    t0s[c] = siluf(a);
    __syncthreads();
    float b = bp1[c];
#pragma unroll 8
    for (int k = 0; k < FD; k++) b += t0s[k] * Wp1[k * FD + c];
    t1s[c] = b;
    __syncthreads();
    float d = bpl[c];
#pragma unroll 8
    for (int k = 0; k < FD; k++) d += t1s[k] * Wpl[k * FD + c];
    float nhf = hf + d;
    g_hf[i * FD + c] = nhf;
    if (doNext) {
        t0s[c] = nhf;
        __syncthreads();
        float s1 = 0.f, s2 = be0n[c];
#pragma unroll 8
        for (int k = 0; k < FD; k++) {
            float hv = t0s[k];
            s1 += hv * We0n[(1 + k) * FD + c];
            s2 += hv * We0n[(129 + k) * FD + c];
        }
        g_hs[i * FD + c] = s1;
        g_hr[i * FD + c] = s2;
    }
}

__global__ void kout(const float* __restrict__ Wv,
                     const float* __restrict__ Wr, const float* __restrict__ br,
                     float* __restrict__ out)
{
    __shared__ float red[FD], p[FD];
    int i = blockIdx.x, c = threadIdx.x;
    float hf = g_hf[i * FD + c];
    red[c] = hf;
    __syncthreads();
    for (int s = 64; s > 0; s >>= 1) {
        if (c < s) red[c] = fmaxf(red[c], red[c + s]);
        __syncthreads();
    }
    float mx = red[0];
    __syncthreads();
    float ex = __expf(hf - mx);
    red[c] = ex;
    __syncthreads();
    for (int s = 64; s > 0; s >>= 1) {
        if (c < s) red[c] += red[c + s];
        __syncthreads();
    }
    float inv = 1.f / red[0];
    __syncthreads();
    p[c] = ex * inv;
    __syncthreads();
    if (c < 32) {
        float a = br[c];
#pragma unroll 8
        for (int k = 0; k < FD; k++) a += p[k] * Wr[k * 32 + c];
        out[NN * 6 + i * 32 + c] = a;
    }
    if (c < 6) {
        int o = c / 3, cc = c % 3;
        out[i * 6 + c] = (g_vec[i * 3 + cc] - g_vec0[i * 3 + cc]) * Wv[o];
    }
}

extern "C" void kernel_launch(void* const* d_in, const int* in_sizes, int n_in,
                              void* d_out, int out_size)
{
    const float* x   = (const float*)d_in[0];
    const float* h   = (const float*)d_in[1];
    const int* snd   = (const int*)  d_in[2];
    const float* Wh0 = (const float*)d_in[4];
    const float* bh0 = (const float*)d_in[5];
    const float* We0 = (const float*)d_in[6];
    const float* be0 = (const float*)d_in[7];
    const float* We1 = (const float*)d_in[8];
    const float* be1 = (const float*)d_in[9];
    const float* We2 = (const float*)d_in[10];
    const float* be2 = (const float*)d_in[11];
    const float* Winf= (const float*)d_in[12];
    const float* binf= (const float*)d_in[13];
    const float* Wx0 = (const float*)d_in[14];
    const float* bx0 = (const float*)d_in[15];
    const float* Wx1 = (const float*)d_in[16];
    const float* bx1 = (const float*)d_in[17];
    const float* Wxo = (const float*)d_in[18];
    const float* bxo = (const float*)d_in[19];
    const float* Wp0 = (const float*)d_in[20];
    const float* bp0 = (const float*)d_in[21];
    const float* Wp1 = (const float*)d_in[22];
    const float* bp1 = (const float*)d_in[23];
    const float* Wpl = (const float*)d_in[24];
    const float* bpl = (const float*)d_in[25];
    const float* Wv  = (const float*)d_in[26];
    const float* Wr  = (const float*)d_in[27];
    const float* br  = (const float*)d_in[28];
    float* out = (float*)d_out;

    int smem = (int)sizeof(ES);
    cudaFuncSetAttribute(kedge, cudaFuncAttributeMaxDynamicSharedMemorySize, smem);
    cudaFuncSetAttribute(kwprep, cudaFuncAttributeMaxDynamicSharedMemorySize, 65536);

    const int WB = FD * FD, W0B = 257 * FD, WP0 = 2 * FD * FD;

    ksetup<<<1, 256>>>(x);
    knode0<<<NN, FD>>>(h, Wh0, bh0, We0, be0);
    kwprep<<<6, 256, 65536>>>(We1, We2, Wx0, Wx1, Winf, be2, bx0, binf);

    for (int b = 0; b < 2; b++) {
        kedge<<<NN, NTHR, smem>>>(snd, We0 + b * W0B,
            be1 + b * FD, bx1 + b * FD, Wxo + b * FD, bxo + b,
            We2 + b * WB, be2 + b * FD, b);
        knode<<<NN, FD>>>(Wp0 + b * WP0, bp0 + b * FD,
                          Wp1 + b * WB, bp1 + b * FD,
                          Wpl + b * WB, bpl + b * FD,
                          We0 + W0B, be0 + FD, b == 0 ? 1 : 0);
    }
    kout<<<NN, FD>>>(Wv, Wr, br, out);
}

// round 16
// speedup vs baseline: 1.1354x; 1.1354x over previous
#include <cuda_runtime.h>
#include <cuda_bf16.h>
#include <math.h>

#define NN    512
#define EPN   511
#define FD    128
#define TILE  64
#define NTILE 8
#define NTHR  256

__device__ float g_vec0[NN * 3];
__device__ float g_vec [NN * 3];
__device__ float g_hf  [NN * FD];
__device__ float g_hs  [NN * FD];
__device__ float g_hr  [NN * FD];
__device__ float g_magg[NN * FD];
__device__ float g_vac [NN * 3];
// 6 matrices (2 blocks x {We1, Wc=We2@Wx0, Wx1}) as T[n][k] images, 64KB each: [hi|lo]
__device__ __align__(16) __nv_bfloat16 g_wb[6 * 32768];
// per block: [0..127] we2winf, [128..255] bc, [256] binf'
__device__ float g_aux[2 * 257];

__device__ __forceinline__ float siluf(float x) {
    return __fdividef(x, 1.f + __expf(-x));
}
__device__ __forceinline__ float sigmf(float x) {
    return __fdividef(1.f, 1.f + __expf(-x));
}

__device__ __forceinline__ unsigned smem_u32(const void* p) {
    unsigned a;
    asm("{ .reg .u64 t; cvta.to.shared.u64 t, %1; cvt.u32.u64 %0, t; }" : "=r"(a) : "l"(p));
    return a;
}
__device__ __forceinline__ void cpasync16(unsigned d, const void* g) {
    asm volatile("cp.async.cg.shared.global [%0], [%1], 16;" :: "r"(d), "l"(g));
}
#define CP_COMMIT() asm volatile("cp.async.commit_group;" ::: "memory")
#define CP_WAIT0()  asm volatile("cp.async.wait_group 0;"  ::: "memory")
#define BAR_PAIR(id) asm volatile("bar.sync %0, 64;" :: "r"(id) : "memory")

__device__ __forceinline__ void ldsm4(unsigned* r, unsigned a) {
    asm volatile("ldmatrix.sync.aligned.m8n8.x4.shared.b16 {%0,%1,%2,%3}, [%4];"
        : "=r"(r[0]), "=r"(r[1]), "=r"(r[2]), "=r"(r[3]) : "r"(a));
}
__device__ __forceinline__ void mma16816(float* c, const unsigned* a,
                                         unsigned b0, unsigned b1) {
    asm volatile("mma.sync.aligned.m16n8k16.row.col.f32.bf16.bf16.f32 "
        "{%0,%1,%2,%3}, {%4,%5,%6,%7}, {%8,%9}, {%0,%1,%2,%3};"
        : "+f"(c[0]), "+f"(c[1]), "+f"(c[2]), "+f"(c[3])
        : "r"(a[0]), "r"(a[1]), "r"(a[2]), "r"(a[3]), "r"(b0), "r"(b1));
}

// image layout: row-major [row][k], 256B rows, 16B chunks XOR-swizzled by row&7
__device__ __forceinline__ int img_off(int e, int c) {
    return (e << 8) + ((((c >> 3) ^ (e & 7))) << 4) + ((c & 7) << 1);
}
__device__ __forceinline__ void st_split2(char* hb, char* lb, int off,
                                          float v0, float v1) {
    __nv_bfloat16 h0 = __float2bfloat16(v0), h1 = __float2bfloat16(v1);
    __nv_bfloat16 l0 = __float2bfloat16(v0 - __bfloat162float(h0));
    __nv_bfloat16 l1 = __float2bfloat16(v1 - __bfloat162float(h1));
    *reinterpret_cast<unsigned*>(hb + off) =
        (unsigned)__bfloat16_as_ushort(h0) | ((unsigned)__bfloat16_as_ushort(h1) << 16);
    *reinterpret_cast<unsigned*>(lb + off) =
        (unsigned)__bfloat16_as_ushort(l0) | ((unsigned)__bfloat16_as_ushort(l1) << 16);
}

struct __align__(16) ES {
    char xhi[16384]; char xlo[16384];   // act0 / Y2 images [e][k], 64 rows
    char yhi[16384]; char ylo[16384];   // G1 output images
    char bbuf[32768];                   // weight term; 4 x 8KB pair regions
    float dv[3 * TILE], len[TILE], l2[TILE], gate[TILE], pxs[TILE];
    float gpart[4 * TILE];
    float w0[FD], hrb[FD], winf[FD], wxo[FD];
    float bb1[FD], bb2[FD], bbx1[FD];
    float maggs[2 * FD], vred[3 * TILE], vaccs[4], rvec[3];
    int   sidx[TILE];
};

// pair (64 threads, pl=0..63) loads its 8KB region: rows [32g, 32g+32) of one term
__device__ __forceinline__ void loadBpair(char* dstreg, const __nv_bfloat16* srcreg,
                                          int pl) {
    unsigned sd = smem_u32(dstreg);
    const float4* s4 = reinterpret_cast<const float4*>(srcreg);
#pragma unroll
    for (int q = 0; q < 8; q++) { int u = pl + q * 64; cpasync16(sd + u * 16, s4 + u); }
    CP_COMMIT();
}

// C[64e][128c] = split3( A @ W ); 8 warps, each a 32e x 32c tile.
// Weight staging PAIR-SCOPED. FOLD (G1 only): computes gate from the DOT
// partials, then ys += gate*silu(acc+bias) and gs += gate from live regs.
template <bool ACT, bool DOT, bool STORE, bool FOLD = false>
__device__ __forceinline__ void gemm_tc(ES* S, const char* Ahi, const char* Alo,
                                        const __nv_bfloat16* wcur,
                                        const __nv_bfloat16* wnext,
                                        const float* bias, const float* dw,
                                        char* Ohi, char* Olo, int t,
                                        float binf_s = 0.f, int tile = 0)
{
    const int w = t >> 5, lane = t & 31;
    const int g = w & 3;
    const int e0 = (w >> 2) * 32, c0 = g * 32;
    const int pl = ((w >> 2) << 5) | lane;
    char* breg = S->bbuf + g * 8192;
    const unsigned l7 = lane & 7;
    float acc[2][4][4];
#pragma unroll
    for (int mt = 0; mt < 2; mt++)
#pragma unroll
        for (int nt = 0; nt < 4; nt++)
#pragma unroll
            for (int q = 0; q < 4; q++) acc[mt][nt][q] = 0.f;

    const unsigned arow = e0 + (lane & 15);
    const unsigned acb  = lane >> 4;
    const unsigned browl = ((lane >> 4) << 3) + l7;
    const unsigned bcb  = (lane >> 3) & 1;
    const unsigned abh = smem_u32(Ahi) + arow * 256;
    const unsigned abl = smem_u32(Alo) + arow * 256;
    const unsigned bb  = smem_u32(breg) + browl * 256;

    CP_WAIT0();                      // W_hi region (issued by prev gemm) arrived
    BAR_PAIR(g + 1);

    // ---- pass 1: B = W_hi; hi-MMAs then lo-MMAs ----
#pragma unroll
    for (int ks = 0; ks < 8; ks++) {
        unsigned ach = (((unsigned)(ks << 1)) | acb) ^ l7;
        unsigned bch = (((unsigned)(ks << 1)) | bcb) ^ l7;
        unsigned ah0[4], ah1[4], al0[4], al1[4], b0[4], b1[4];
        ldsm4(ah0, abh + (ach << 4));
        ldsm4(ah1, abh + 16 * 256 + (ach << 4));
        ldsm4(al0, abl + (ach << 4));
        ldsm4(al1, abl + 16 * 256 + (ach << 4));
        ldsm4(b0, bb + (bch << 4));
        ldsm4(b1, bb + 16 * 256 + (bch << 4));
        mma16816(acc[0][0], ah0, b0[0], b0[1]); mma16816(acc[0][1], ah0, b0[2], b0[3]);
        mma16816(acc[1][0], ah1, b0[0], b0[1]); mma16816(acc[1][1], ah1, b0[2], b0[3]);
        mma16816(acc[0][2], ah0, b1[0], b1[1]); mma16816(acc[0][3], ah0, b1[2], b1[3]);
        mma16816(acc[1][2], ah1, b1[0], b1[1]); mma16816(acc[1][3], ah1, b1[2], b1[3]);
        mma16816(acc[0][0], al0, b0[0], b0[1]); mma16816(acc[0][1], al0, b0[2], b0[3]);
        mma16816(acc[1][0], al1, b0[0], b0[1]); mma16816(acc[1][1], al1, b0[2], b0[3]);
        mma16816(acc[0][2], al0, b1[0], b1[1]); mma16816(acc[0][3], al0, b1[2], b1[3]);
        mma16816(acc[1][2], al1, b1[0], b1[1]); mma16816(acc[1][3], al1, b1[2], b1[3]);
    }
    BAR_PAIR(g + 1);                               // pair done reading W_hi
    loadBpair(breg, wcur + 16384 + g * 4096, pl);  // swap in W_lo region
    CP_WAIT0();
    BAR_PAIR(g + 1);

    // ---- pass 2: B = W_lo; A = hi only ----
#pragma unroll
    for (int ks = 0; ks < 8; ks++) {
        unsigned ach = (((unsigned)(ks << 1)) | acb) ^ l7;
        unsigned bch = (((unsigned)(ks << 1)) | bcb) ^ l7;
        unsigned ah0[4], ah1[4];
        ldsm4(ah0, abh + (ach << 4));
        ldsm4(ah1, abh + 16 * 256 + (ach << 4));
#pragma unroll
        for (int p = 0; p < 2; p++) {
            unsigned b[4];
            ldsm4(b, bb + p * 16 * 256 + (bch << 4));
            mma16816(acc[0][2 * p],     ah0, b[0], b[1]);
            mma16816(acc[0][2 * p + 1], ah0, b[2], b[3]);
            mma16816(acc[1][2 * p],     ah1, b[0], b[1]);
            mma16816(acc[1][2 * p + 1], ah1, b[2], b[3]);
        }
    }
    BAR_PAIR(g + 1);                         // pair done reading W_lo
    loadBpair(breg, wnext + g * 4096, pl);   // prefetch next matrix W_hi region

    const int r = lane >> 2, n2 = (lane & 3) * 2;
    float drow[2][2] = {{0.f, 0.f}, {0.f, 0.f}};
#pragma unroll
    for (int mt = 0; mt < 2; mt++) {
        int eA = e0 + mt * 16 + r;
#pragma unroll
        for (int nt = 0; nt < 4; nt++) {
            int c = c0 + nt * 8 + n2;
            float b0v = bias[c], b1v = bias[c + 1];
            float v00 = acc[mt][nt][0] + b0v, v01 = acc[mt][nt][1] + b1v;
            float v10 = acc[mt][nt][2] + b0v, v11 = acc[mt][nt][3] + b1v;
            if (ACT) { v00 = siluf(v00); v01 = siluf(v01);
                       v10 = siluf(v10); v11 = siluf(v11); }
            if (DOT) {
                drow[mt][0] += v00 * dw[c] + v01 * dw[c + 1];
                drow[mt][1] += v10 * dw[c] + v11 * dw[c + 1];
            }
            if (STORE) {
                st_split2(Ohi, Olo, img_off(eA, c), v00, v01);
                st_split2(Ohi, Olo, img_off(eA + 8, c), v10, v11);
            }
        }
    }
    if (DOT) {
#pragma unroll
        for (int mt = 0; mt < 2; mt++)
#pragma unroll
            for (int hb = 0; hb < 2; hb++) {
                float v = drow[mt][hb];
                v += __shfl_xor_sync(0xffffffffu, v, 1);
                v += __shfl_xor_sync(0xffffffffu, v, 2);
                if ((lane & 3) == 0)
                    S->gpart[g * TILE + e0 + mt * 16 + hb * 8 + r] = v;
            }
    }

    if (FOLD) {
        __syncthreads();                      // gpart complete across warps
        if (t < TILE) {
            bool valid = (tile * TILE + t) < EPN;
            S->gate[t] = valid ? sigmf(binf_s + S->gpart[t] + S->gpart[TILE + t]
                                       + S->gpart[2 * TILE + t] + S->gpart[3 * TILE + t])
                               : 0.f;
        }
        __syncthreads();                      // gate visible
        if (t < 32) {                         // gs += sum(gate)
            float v = S->gate[t] + S->gate[t + 32];
#pragma unroll
            for (int o = 16; o; o >>= 1) v += __shfl_down_sync(0xffffffffu, v, o);
            if (t == 0) S->vaccs[3] += v;
        }
        // ys fold from live acc: ys[c] += sum_e gate[e]*silu(acc+bias)
        float mc[4][2];
#pragma unroll
        for (int nt = 0; nt < 4; nt++) { mc[nt][0] = 0.f; mc[nt][1] = 0.f; }
#pragma unroll
        for (int mt = 0; mt < 2; mt++) {
            float gA = S->gate[e0 + mt * 16 + r];
            float gB = S->gate[e0 + mt * 16 + 8 + r];
#pragma unroll
            for (int nt = 0; nt < 4; nt++) {
                int c = c0 + nt * 8 + n2;
                float b0v = bias[c], b1v = bias[c + 1];
                mc[nt][0] += gA * siluf(acc[mt][nt][0] + b0v)
                           + gB * siluf(acc[mt][nt][2] + b0v);
                mc[nt][1] += gA * siluf(acc[mt][nt][1] + b1v)
                           + gB * siluf(acc[mt][nt][3] + b1v);
            }
        }
#pragma unroll
        for (int nt = 0; nt < 4; nt++)
#pragma unroll
            for (int j = 0; j < 2; j++) {
                float v = mc[nt][j];
                v += __shfl_xor_sync(0xffffffffu, v, 4);
                v += __shfl_xor_sync(0xffffffffu, v, 8);
                v += __shfl_xor_sync(0xffffffffu, v, 16);
                mc[nt][j] = v;
            }
        if (lane < 4) {
            int eg = w >> 2;
#pragma unroll
            for (int nt = 0; nt < 4; nt++)
#pragma unroll
                for (int j = 0; j < 2; j++) {
                    int c = c0 + nt * 8 + lane * 2 + j;
                    S->maggs[eg * FD + c] += mc[nt][j];
                }
        }
    }
}

__global__ void __launch_bounds__(NTHR, 2)
kedge(const int* __restrict__ senders, const float* __restrict__ We0r0,
      const float* __restrict__ be1, const float* __restrict__ bx1,
      const float* __restrict__ Wxo, const float* __restrict__ bxop,
      const float* __restrict__ We2g, const float* __restrict__ be2g, int blk)
{
    extern __shared__ char smraw[];
    ES* S = reinterpret_cast<ES*>(smraw);
    const int t = threadIdx.x, i = blockIdx.x;
    const int w = t >> 5, lane = t & 31;
    const int g = w & 3;
    const int pl = ((w >> 2) << 5) | lane;
    const __nv_bfloat16* wb = g_wb + blk * 3 * 32768;
    const float* aux = g_aux + blk * 257;

    if (t < FD) {
        S->w0[t] = We0r0[t]; S->hrb[t] = g_hr[i * FD + t];
        S->winf[t] = aux[t];            // we2winf
        S->bb2[t] = aux[FD + t];        // bc
        S->wxo[t] = Wxo[t];
        S->bb1[t] = be1[t]; S->bbx1[t] = bx1[t];
    }
    S->maggs[t] = 0.f;
    if (t < 4) S->vaccs[t] = 0.f;
    if (t < 3) S->rvec[t] = g_vec[i * 3 + t];
    const float binf_s = aux[256], bxo_s = bxop[0];

    loadBpair(S->bbuf + g * 8192, wb + g * 4096, pl);   // We1 hi, pair region
    __syncthreads();

    for (int tile = 0; tile < NTILE; tile++) {
        if (t < TILE) {                                  // stage 1
            int je = tile * TILE + t;
            bool valid = je < EPN;
            int s = valid ? senders[i * EPN + je] : i;
            S->sidx[t] = s;
            float d0 = 0.f, d1 = 0.f, d2 = 0.f;
            if (valid) {
                d0 = S->rvec[0] - g_vec[s * 3 + 0];
                d1 = S->rvec[1] - g_vec[s * 3 + 1];
                d2 = S->rvec[2] - g_vec[s * 3 + 2];
            }
            S->dv[t * 3] = d0; S->dv[t * 3 + 1] = d1; S->dv[t * 3 + 2] = d2;
            float dot = d0 * d0 + d1 * d1 + d2 * d2 + 1e-20f;
            S->l2[t] = valid ? dot : 0.f;
            S->len[t] = sqrtf(dot);
        }
        __syncthreads();
        {                                                // stage 2: act0 -> X
            int e = t >> 2, kh = t & 3;
            int s = S->sidx[e];
            float l2v = S->l2[e];
            const float* hsr = g_hs + s * FD + kh * 32;
#pragma unroll 8
            for (int j = 0; j < 32; j += 2) {
                int c = kh * 32 + j;
                float v0 = siluf(l2v * S->w0[c]     + hsr[j]     + S->hrb[c]);
                float v1 = siluf(l2v * S->w0[c + 1] + hsr[j + 1] + S->hrb[c + 1]);
                st_split2(S->xhi, S->xlo, img_off(e, c), v0, v1);
            }
        }
        __syncthreads();

        // G1: Y = silu(X @ We1 + be1); gate dot (we2winf) + ys/gs fold
        gemm_tc<true, true, true, true>(S, S->xhi, S->xlo,
                                   wb + 0 * 32768, wb + 1 * 32768,
                                   S->bb1, S->winf, S->yhi, S->ylo, t,
                                   binf_s, tile);
        __syncthreads();

        // G3': Y2 = silu(Y @ Wc + bc)   (Wc = We2@Wx0 precomputed)
        gemm_tc<true, false, true>(S, S->yhi, S->ylo,
                                   wb + 1 * 32768, wb + 2 * 32768,
                                   S->bb2, 0, S->xhi, S->xlo, t);
        __syncthreads();

        // G4: px partial = silu(Y2 @ Wx1 + bx1) . wxo  (no store); next = We1
        gemm_tc<true, true, false>(S, S->xhi, S->xlo,
                                   wb + 2 * 32768, wb + 0 * 32768,
                                   S->bbx1, S->wxo, S->yhi, S->ylo, t);
        __syncthreads();
        if (t < TILE)
            S->pxs[t] = __fdividef(bxo_s + S->gpart[t] + S->gpart[TILE + t]
                                   + S->gpart[2 * TILE + t] + S->gpart[3 * TILE + t],
                                   1.f + S->len[t]);
        __syncthreads();
        if (t < TILE) {                                  // vac partial
            float p = S->pxs[t];
            S->vred[t] = p * S->dv[t * 3];
            S->vred[TILE + t] = p * S->dv[t * 3 + 1];
            S->vred[2 * TILE + t] = p * S->dv[t * 3 + 2];
        }
        __syncthreads();
        if (t < 96) {
            int c = t >> 5, l = t & 31;
            const float* vr = S->vred + c * TILE;
            float v = vr[l] + vr[l + 32];
#pragma unroll
            for (int o = 16; o; o >>= 1) v += __shfl_down_sync(0xffffffffu, v, o);
            if (l == 0) S->vaccs[c] += v;
        }
        __syncthreads();
    }

    // writeout: magg = (ys @ We2) + gs*be2, scaled
    if (t < FD) S->gpart[t] = S->maggs[t] + S->maggs[FD + t];   // ys
    __syncthreads();
    if (t < FD) {
        float a = S->vaccs[3] * be2g[t];
#pragma unroll 8
        for (int k = 0; k < FD; k++) a += S->gpart[k] * We2g[k * FD + t];
        g_magg[i * FD + t] = a * rsqrtf(511.f);
    }
    if (t < 3) g_vac[i * 3 + t] = S->vaccs[t] * (1.f / 511.f);
}

// weights -> T[n][k] bf16 hi/lo swizzled images.
// grid 6: m = b*3+g; g0: We1 copy, g1: Wc = We2@Wx0 (smem-staged matmul) + aux,
// g2: Wx1 copy
__global__ void __launch_bounds__(256) kwprep(
    const float* __restrict__ We1, const float* __restrict__ We2,
    const float* __restrict__ Wx0, const float* __restrict__ Wx1,
    const float* __restrict__ Winf, const float* __restrict__ be2,
    const float* __restrict__ bx0, const float* __restrict__ binf)
{
    extern __shared__ float sW[];          // 128KB: [Wx0 | We2] fp32
    int m = blockIdx.x, b = m / 3, g = m % 3;
    int t = threadIdx.x;
    char* blob = reinterpret_cast<char*>(g_wb + m * 32768);

    if (g == 1) {
        const float* We2g = We2 + b * FD * FD;
        const float* Wx0g = Wx0 + b * FD * FD;
        const float* winfg = Winf + b * FD;
        const float* be2g = be2 + b * FD;
        const float* bx0g = bx0 + b * FD;
        float* sA = sW;                  // Wx0
        float* sB = sW + FD * FD;        // We2
        float* aux = g_aux + b * 257;
        for (int idx = t; idx < FD * FD; idx += 256) {
            sA[idx] = Wx0g[idx];
            sB[idx] = We2g[idx];
        }
        __syncthreads();
        for (int ii = 0; ii < 64; ii++) {
            int idx = t + ii * 256;
            int k = idx >> 7, n = idx & 127;
            const float* br = sB + k * FD;
            float a0 = 0.f, a1 = 0.f, a2 = 0.f, a3 = 0.f;
#pragma unroll 8
            for (int j = 0; j < FD; j += 4) {
                a0 += br[j]     * sA[j * FD + n];
                a1 += br[j + 1] * sA[(j + 1) * FD + n];
                a2 += br[j + 2] * sA[(j + 2) * FD + n];
                a3 += br[j + 3] * sA[(j + 3) * FD + n];
            }
            float a = (a0 + a1) + (a2 + a3);
            __nv_bfloat16 h = __float2bfloat16(a);
            __nv_bfloat16 l = __float2bfloat16(a - __bfloat162float(h));
            int off = (n << 8) + ((((k >> 3) ^ (n & 7))) << 4) + ((k & 7) << 1);
            *reinterpret_cast<__nv_bfloat16*>(blob + off) = h;
            *reinterpret_cast<__nv_bfloat16*>(blob + 32768 + off) = l;
        }
        if (t < FD) {
            float a = 0.f;
#pragma unroll 8
            for (int c = 0; c < FD; c++) a += sB[t * FD + c] * winfg[c];
            aux[t] = a;                       // we2winf
            float bcv = bx0g[t];
#pragma unroll 8
            for (int j = 0; j < FD; j++) bcv += be2g[j] * sA[j * FD + t];
            aux[FD + t] = bcv;                // bc
        }
        if (t == 0) {
            float a = binf[b];
#pragma unroll 8
            for (int c = 0; c < FD; c++) a += be2g[c] * winfg[c];
            aux[256] = a;                     // binf'
        }
        return;
    }

    const float* W = (g == 0 ? We1 : Wx1) + b * FD * FD;
    int n = t & 127, kh = t >> 7;
    for (int kc = 0; kc < 8; kc++) {
        int kchunk = kh * 8 + kc;
        unsigned qh[4], ql[4];
#pragma unroll
        for (int u = 0; u < 4; u++) {
            int k = kchunk * 8 + u * 2;
            float x0 = W[k * FD + n], x1 = W[(k + 1) * FD + n];
            __nv_bfloat16 h0 = __float2bfloat16(x0), h1 = __float2bfloat16(x1);
            __nv_bfloat16 l0 = __float2bfloat16(x0 - __bfloat162float(h0));
            __nv_bfloat16 l1 = __float2bfloat16(x1 - __bfloat162float(h1));
            qh[u] = (unsigned)__bfloat16_as_ushort(h0) | ((unsigned)__bfloat16_as_ushort(h1) << 16);
            ql[u] = (unsigned)__bfloat16_as_ushort(l0) | ((unsigned)__bfloat16_as_ushort(l1) << 16);
        }
        int off = (n << 8) + ((kchunk ^ (n & 7)) << 4);
        *reinterpret_cast<uint4*>(blob + off)         = make_uint4(qh[0], qh[1], qh[2], qh[3]);
        *reinterpret_cast<uint4*>(blob + 32768 + off) = make_uint4(ql[0], ql[1], ql[2], ql[3]);
    }
}

__global__ void ksetup(const float* __restrict__ x)
{
    __shared__ float r0[256], r1[256], r2[256];
    __shared__ float mean[3];
    int t = threadIdx.x;
    float s0 = 0.f, s1 = 0.f, s2 = 0.f;
    for (int n = t; n < NN; n += 256) {
        s0 += x[n * 3]; s1 += x[n * 3 + 1]; s2 += x[n * 3 + 2];
    }
    r0[t] = s0; r1[t] = s1; r2[t] = s2;
    __syncthreads();
    for (int s = 128; s > 0; s >>= 1) {
        if (t < s) { r0[t] += r0[t + s]; r1[t] += r1[t + s]; r2[t] += r2[t + s]; }
        __syncthreads();
    }
    if (t == 0) { mean[0] = r0[0] / NN; mean[1] = r1[0] / NN; mean[2] = r2[0] / NN; }
    __syncthreads();
    for (int n = t; n < NN; n += 256)
#pragma unroll
        for (int c = 0; c < 3; c++) {
            float v = x[n * 3 + c] - mean[c];
            g_vec[n * 3 + c] = v; g_vec0[n * 3 + c] = v;
        }
}

__global__ void knode0(const float* __restrict__ h,
                       const float* __restrict__ Wh0, const float* __restrict__ bh0,
                       const float* __restrict__ We0, const float* __restrict__ be0)
{
    __shared__ float hrow[16];
    __shared__ float hfs[FD];
    int i = blockIdx.x, c = threadIdx.x;
    if (c < 16) hrow[c] = h[i * 16 + c];
    __syncthreads();
    float acc = bh0[c];
#pragma unroll
    for (int k = 0; k < 16; k++) acc += hrow[k] * Wh0[k * FD + c];
    g_hf[i * FD + c] = acc;
    hfs[c] = acc;
    __syncthreads();
    float s1 = 0.f, s2 = be0[c];
#pragma unroll 8
    for (int k = 0; k < FD; k++) {
        float hv = hfs[k];
        s1 += hv * We0[(1 + k) * FD + c];
        s2 += hv * We0[(129 + k) * FD + c];
    }
    g_hs[i * FD + c] = s1;
    g_hr[i * FD + c] = s2;
}

__global__ void knode(const float* __restrict__ Wp0, const float* __restrict__ bp0,
                      const float* __restrict__ Wp1, const float* __restrict__ bp1,
                      const float* __restrict__ Wpl, const float* __restrict__ bpl,
                      const float* __restrict__ We0n, const float* __restrict__ be0n,
                      int doNext)
{
    __shared__ float in0[2 * FD], t0s[FD], t1s[FD];
    int i = blockIdx.x, c = threadIdx.x;
    if (c < 3) g_vec[i * 3 + c] += g_vac[i * 3 + c];
    in0[c] = g_magg[i * FD + c];
    float hf = g_hf[i * FD + c];
    in0[FD + c] = hf;
    __syncthreads();
    float a = bp0[c];
#pragma unroll 8
    for (int k = 0; k < 2 * FD; k++) a += in0[k] * Wp0[k * FD + c];
    t0s[c] = siluf(a);
    __syncthreads();
    float b = bp1[c];
#pragma unroll 8
    for (int k = 0; k < FD; k++) b += t0s[k] * Wp1[k * FD + c];
    t1s[c] = b;
    __syncthreads();
    float d = bpl[c];
#pragma unroll 8
    for (int k = 0; k < FD; k++) d += t1s[k] * Wpl[k * FD + c];
    float nhf = hf + d;
    g_hf[i * FD + c] = nhf;
    if (doNext) {
        t0s[c] = nhf;
        __syncthreads();
        float s1 = 0.f, s2 = be0n[c];
#pragma unroll 8
        for (int k = 0; k < FD; k++) {
            float hv = t0s[k];
            s1 += hv * We0n[(1 + k) * FD + c];
            s2 += hv * We0n[(129 + k) * FD + c];
        }
        g_hs[i * FD + c] = s1;
        g_hr[i * FD + c] = s2;
    }
}

__global__ void kout(const float* __restrict__ Wv,
                     const float* __restrict__ Wr, const float* __restrict__ br,
                     float* __restrict__ out)
{
    __shared__ float red[FD], p[FD];
    int i = blockIdx.x, c = threadIdx.x;
    float hf = g_hf[i * FD + c];
    red[c] = hf;
    __syncthreads();
    for (int s = 64; s > 0; s >>= 1) {
        if (c < s) red[c] = fmaxf(red[c], red[c + s]);
        __syncthreads();
    }
    float mx = red[0];
    __syncthreads();
    float ex = __expf(hf - mx);
    red[c] = ex;
    __syncthreads();
    for (int s = 64; s > 0; s >>= 1) {
        if (c < s) red[c] += red[c + s];
        __syncthreads();
    }
    float inv = 1.f / red[0];
    __syncthreads();
    p[c] = ex * inv;
    __syncthreads();
    if (c < 32) {
        float a = br[c];
#pragma unroll 8
        for (int k = 0; k < FD; k++) a += p[k] * Wr[k * 32 + c];
        out[NN * 6 + i * 32 + c] = a;
    }
    if (c < 6) {
        int o = c / 3, cc = c % 3;
        out[i * 6 + c] = (g_vec[i * 3 + cc] - g_vec0[i * 3 + cc]) * Wv[o];
    }
}

extern "C" void kernel_launch(void* const* d_in, const int* in_sizes, int n_in,
                              void* d_out, int out_size)
{
    const float* x   = (const float*)d_in[0];
    const float* h   = (const float*)d_in[1];
    const int* snd   = (const int*)  d_in[2];
    const float* Wh0 = (const float*)d_in[4];
    const float* bh0 = (const float*)d_in[5];
    const float* We0 = (const float*)d_in[6];
    const float* be0 = (const float*)d_in[7];
    const float* We1 = (const float*)d_in[8];
    const float* be1 = (const float*)d_in[9];
    const float* We2 = (const float*)d_in[10];
    const float* be2 = (const float*)d_in[11];
    const float* Winf= (const float*)d_in[12];
    const float* binf= (const float*)d_in[13];
    const float* Wx0 = (const float*)d_in[14];
    const float* bx0 = (const float*)d_in[15];
    const float* Wx1 = (const float*)d_in[16];
    const float* bx1 = (const float*)d_in[17];
    const float* Wxo = (const float*)d_in[18];
    const float* bxo = (const float*)d_in[19];
    const float* Wp0 = (const float*)d_in[20];
    const float* bp0 = (const float*)d_in[21];
    const float* Wp1 = (const float*)d_in[22];
    const float* bp1 = (const float*)d_in[23];
    const float* Wpl = (const float*)d_in[24];
    const float* bpl = (const float*)d_in[25];
    const float* Wv  = (const float*)d_in[26];
    const float* Wr  = (const float*)d_in[27];
    const float* br  = (const float*)d_in[28];
    float* out = (float*)d_out;

    int smem = (int)sizeof(ES);
    cudaFuncSetAttribute(kedge, cudaFuncAttributeMaxDynamicSharedMemorySize, smem);
    cudaFuncSetAttribute(kwprep, cudaFuncAttributeMaxDynamicSharedMemorySize, 131072);

    const int WB = FD * FD, W0B = 257 * FD, WP0 = 2 * FD * FD;

    ksetup<<<1, 256>>>(x);
    knode0<<<NN, FD>>>(h, Wh0, bh0, We0, be0);
    kwprep<<<6, 256, 131072>>>(We1, We2, Wx0, Wx1, Winf, be2, bx0, binf);

    for (int b = 0; b < 2; b++) {
        kedge<<<NN, NTHR, smem>>>(snd, We0 + b * W0B,
            be1 + b * FD, bx1 + b * FD, Wxo + b * FD, bxo + b,
            We2 + b * WB, be2 + b * FD, b);
        knode<<<NN, FD>>>(Wp0 + b * WP0, bp0 + b * FD,
                          Wp1 + b * WB, bp1 + b * FD,
                          Wpl + b * WB, bpl + b * FD,
                          We0 + W0B, be0 + FD, b == 0 ? 1 : 0);
    }
    kout<<<NN, FD>>>(Wv, Wr, br, out);
}

// round 17
// speedup vs baseline: 1.1452x; 1.0087x over previous
#include <cuda_runtime.h>
#include <cuda_bf16.h>
#include <math.h>

#define NN    512
#define EPN   511
#define FD    128
#define TILE  64
#define NTILE 8
#define NTHR  256

__device__ float g_vec0[NN * 3];
__device__ float g_vec [NN * 3];
__device__ float g_hf  [NN * FD];
__device__ float g_hs  [NN * FD];
__device__ float g_hr  [NN * FD];
__device__ float g_magg[NN * FD];
__device__ float g_vac [NN * 3];
// 6 matrices (2 blocks x {We1, Wc=We2@Wx0, Wx1}) as T[n][k] images, 64KB each: [hi|lo]
__device__ __align__(16) __nv_bfloat16 g_wb[6 * 32768];
// per block: [0..127] we2winf, [128..255] bc, [256] binf'
__device__ float g_aux[2 * 257];

__device__ __forceinline__ float siluf(float x) {
    return __fdividef(x, 1.f + __expf(-x));
}
__device__ __forceinline__ float sigmf(float x) {
    return __fdividef(1.f, 1.f + __expf(-x));
}

__device__ __forceinline__ unsigned smem_u32(const void* p) {
    unsigned a;
    asm("{ .reg .u64 t; cvta.to.shared.u64 t, %1; cvt.u32.u64 %0, t; }" : "=r"(a) : "l"(p));
    return a;
}
__device__ __forceinline__ void cpasync16(unsigned d, const void* g) {
    asm volatile("cp.async.cg.shared.global [%0], [%1], 16;" :: "r"(d), "l"(g));
}
#define CP_COMMIT() asm volatile("cp.async.commit_group;" ::: "memory")
#define CP_WAIT0()  asm volatile("cp.async.wait_group 0;"  ::: "memory")
#define BAR_PAIR(id) asm volatile("bar.sync %0, 64;" :: "r"(id) : "memory")

__device__ __forceinline__ void ldsm4(unsigned* r, unsigned a) {
    asm volatile("ldmatrix.sync.aligned.m8n8.x4.shared.b16 {%0,%1,%2,%3}, [%4];"
        : "=r"(r[0]), "=r"(r[1]), "=r"(r[2]), "=r"(r[3]) : "r"(a));
}
__device__ __forceinline__ void mma16816(float* c, const unsigned* a,
                                         unsigned b0, unsigned b1) {
    asm volatile("mma.sync.aligned.m16n8k16.row.col.f32.bf16.bf16.f32 "
        "{%0,%1,%2,%3}, {%4,%5,%6,%7}, {%8,%9}, {%0,%1,%2,%3};"
        : "+f"(c[0]), "+f"(c[1]), "+f"(c[2]), "+f"(c[3])
        : "r"(a[0]), "r"(a[1]), "r"(a[2]), "r"(a[3]), "r"(b0), "r"(b1));
}

// image layout: row-major [row][k], 256B rows, 16B chunks XOR-swizzled by row&7
__device__ __forceinline__ int img_off(int e, int c) {
    return (e << 8) + ((((c >> 3) ^ (e & 7))) << 4) + ((c & 7) << 1);
}
__device__ __forceinline__ void st_split2(char* hb, char* lb, int off,
                                          float v0, float v1) {
    __nv_bfloat16 h0 = __float2bfloat16(v0), h1 = __float2bfloat16(v1);
    __nv_bfloat16 l0 = __float2bfloat16(v0 - __bfloat162float(h0));
    __nv_bfloat16 l1 = __float2bfloat16(v1 - __bfloat162float(h1));
    *reinterpret_cast<unsigned*>(hb + off) =
        (unsigned)__bfloat16_as_ushort(h0) | ((unsigned)__bfloat16_as_ushort(h1) << 16);
    *reinterpret_cast<unsigned*>(lb + off) =
        (unsigned)__bfloat16_as_ushort(l0) | ((unsigned)__bfloat16_as_ushort(l1) << 16);
}

struct __align__(16) ES {
    char xhi[16384]; char xlo[16384];   // act0 / Y2 images [e][k], 64 rows
    char yhi[16384]; char ylo[16384];   // G1 output images
    char bbuf[32768];                   // weight term; 4 x 8KB pair regions
    float dv[3 * TILE], len[TILE], l2[TILE], gate[TILE];
    float gpart[4 * TILE];
    float w0[FD], hrb[FD], winf[FD], wxo[FD];
    float bb1[FD], bb2[FD], bbx1[FD];
    float maggs[2 * FD], vred[3 * TILE], vaccs[4], rvec[3];
    int   sidx[TILE];
};

// pair (64 threads, pl=0..63) loads its 8KB region: rows [32g, 32g+32) of one term
__device__ __forceinline__ void loadBpair(char* dstreg, const __nv_bfloat16* srcreg,
                                          int pl) {
    unsigned sd = smem_u32(dstreg);
    const float4* s4 = reinterpret_cast<const float4*>(srcreg);
#pragma unroll
    for (int q = 0; q < 8; q++) { int u = pl + q * 64; cpasync16(sd + u * 16, s4 + u); }
    CP_COMMIT();
}

// C[64e][128c] = split3( A @ W ); 8 warps, each a 32e x 32c tile.
// Weight staging PAIR-SCOPED. FOLD (G1 only): computes gate from the DOT
// partials, then ys += gate*silu(acc+bias) and gs += gate from live regs.
template <bool ACT, bool DOT, bool STORE, bool FOLD = false>
__device__ __forceinline__ void gemm_tc(ES* S, const char* Ahi, const char* Alo,
                                        const __nv_bfloat16* wcur,
                                        const __nv_bfloat16* wnext,
                                        const float* bias, const float* dw,
                                        char* Ohi, char* Olo, int t,
                                        float binf_s = 0.f, int tile = 0)
{
    const int w = t >> 5, lane = t & 31;
    const int g = w & 3;
    const int e0 = (w >> 2) * 32, c0 = g * 32;
    const int pl = ((w >> 2) << 5) | lane;
    char* breg = S->bbuf + g * 8192;
    const unsigned l7 = lane & 7;
    float acc[2][4][4];
#pragma unroll
    for (int mt = 0; mt < 2; mt++)
#pragma unroll
        for (int nt = 0; nt < 4; nt++)
#pragma unroll
            for (int q = 0; q < 4; q++) acc[mt][nt][q] = 0.f;

    const unsigned arow = e0 + (lane & 15);
    const unsigned acb  = lane >> 4;
    const unsigned browl = ((lane >> 4) << 3) + l7;
    const unsigned bcb  = (lane >> 3) & 1;
    const unsigned abh = smem_u32(Ahi) + arow * 256;
    const unsigned abl = smem_u32(Alo) + arow * 256;
    const unsigned bb  = smem_u32(breg) + browl * 256;

    CP_WAIT0();                      // W_hi region (issued by prev gemm) arrived
    BAR_PAIR(g + 1);

    // ---- pass 1: B = W_hi; hi-MMAs then lo-MMAs ----
#pragma unroll
    for (int ks = 0; ks < 8; ks++) {
        unsigned ach = (((unsigned)(ks << 1)) | acb) ^ l7;
        unsigned bch = (((unsigned)(ks << 1)) | bcb) ^ l7;
        unsigned ah0[4], ah1[4], al0[4], al1[4], b0[4], b1[4];
        ldsm4(ah0, abh + (ach << 4));
        ldsm4(ah1, abh + 16 * 256 + (ach << 4));
        ldsm4(al0, abl + (ach << 4));
        ldsm4(al1, abl + 16 * 256 + (ach << 4));
        ldsm4(b0, bb + (bch << 4));
        ldsm4(b1, bb + 16 * 256 + (bch << 4));
        mma16816(acc[0][0], ah0, b0[0], b0[1]); mma16816(acc[0][1], ah0, b0[2], b0[3]);
        mma16816(acc[1][0], ah1, b0[0], b0[1]); mma16816(acc[1][1], ah1, b0[2], b0[3]);
        mma16816(acc[0][2], ah0, b1[0], b1[1]); mma16816(acc[0][3], ah0, b1[2], b1[3]);
        mma16816(acc[1][2], ah1, b1[0], b1[1]); mma16816(acc[1][3], ah1, b1[2], b1[3]);
        mma16816(acc[0][0], al0, b0[0], b0[1]); mma16816(acc[0][1], al0, b0[2], b0[3]);
        mma16816(acc[1][0], al1, b0[0], b0[1]); mma16816(acc[1][1], al1, b0[2], b0[3]);
        mma16816(acc[0][2], al0, b1[0], b1[1]); mma16816(acc[0][3], al0, b1[2], b1[3]);
        mma16816(acc[1][2], al1, b1[0], b1[1]); mma16816(acc[1][3], al1, b1[2], b1[3]);
    }
    BAR_PAIR(g + 1);                               // pair done reading W_hi
    loadBpair(breg, wcur + 16384 + g * 4096, pl);  // swap in W_lo region
    CP_WAIT0();
    BAR_PAIR(g + 1);

    // ---- pass 2: B = W_lo; A = hi only ----
#pragma unroll
    for (int ks = 0; ks < 8; ks++) {
        unsigned ach = (((unsigned)(ks << 1)) | acb) ^ l7;
        unsigned bch = (((unsigned)(ks << 1)) | bcb) ^ l7;
        unsigned ah0[4], ah1[4];
        ldsm4(ah0, abh + (ach << 4));
        ldsm4(ah1, abh + 16 * 256 + (ach << 4));
#pragma unroll
        for (int p = 0; p < 2; p++) {
            unsigned b[4];
            ldsm4(b, bb + p * 16 * 256 + (bch << 4));
            mma16816(acc[0][2 * p],     ah0, b[0], b[1]);
            mma16816(acc[0][2 * p + 1], ah0, b[2], b[3]);
            mma16816(acc[1][2 * p],     ah1, b[0], b[1]);
            mma16816(acc[1][2 * p + 1], ah1, b[2], b[3]);
        }
    }
    BAR_PAIR(g + 1);                         // pair done reading W_lo
    loadBpair(breg, wnext + g * 4096, pl);   // prefetch next matrix W_hi region

    const int r = lane >> 2, n2 = (lane & 3) * 2;
    float drow[2][2] = {{0.f, 0.f}, {0.f, 0.f}};
#pragma unroll
    for (int mt = 0; mt < 2; mt++) {
        int eA = e0 + mt * 16 + r;
#pragma unroll
        for (int nt = 0; nt < 4; nt++) {
            int c = c0 + nt * 8 + n2;
            float b0v = bias[c], b1v = bias[c + 1];
            float v00 = acc[mt][nt][0] + b0v, v01 = acc[mt][nt][1] + b1v;
            float v10 = acc[mt][nt][2] + b0v, v11 = acc[mt][nt][3] + b1v;
            if (ACT) { v00 = siluf(v00); v01 = siluf(v01);
                       v10 = siluf(v10); v11 = siluf(v11); }
            if (DOT) {
                drow[mt][0] += v00 * dw[c] + v01 * dw[c + 1];
                drow[mt][1] += v10 * dw[c] + v11 * dw[c + 1];
            }
            if (STORE) {
                st_split2(Ohi, Olo, img_off(eA, c), v00, v01);
                st_split2(Ohi, Olo, img_off(eA + 8, c), v10, v11);
            }
        }
    }
    if (DOT) {
#pragma unroll
        for (int mt = 0; mt < 2; mt++)
#pragma unroll
            for (int hb = 0; hb < 2; hb++) {
                float v = drow[mt][hb];
                v += __shfl_xor_sync(0xffffffffu, v, 1);
                v += __shfl_xor_sync(0xffffffffu, v, 2);
                if ((lane & 3) == 0)
                    S->gpart[g * TILE + e0 + mt * 16 + hb * 8 + r] = v;
            }
    }

    if (FOLD) {
        __syncthreads();                      // gpart complete across warps
        if (t < TILE) {
            bool valid = (tile * TILE + t) < EPN;
            S->gate[t] = valid ? sigmf(binf_s + S->gpart[t] + S->gpart[TILE + t]
                                       + S->gpart[2 * TILE + t] + S->gpart[3 * TILE + t])
                               : 0.f;
        }
        __syncthreads();                      // gate visible
        if (t < 32) {                         // gs += sum(gate)
            float v = S->gate[t] + S->gate[t + 32];
#pragma unroll
            for (int o = 16; o; o >>= 1) v += __shfl_down_sync(0xffffffffu, v, o);
            if (t == 0) S->vaccs[3] += v;
        }
        // ys fold from live acc: ys[c] += sum_e gate[e]*silu(acc+bias)
        float mc[4][2];
#pragma unroll
        for (int nt = 0; nt < 4; nt++) { mc[nt][0] = 0.f; mc[nt][1] = 0.f; }
#pragma unroll
        for (int mt = 0; mt < 2; mt++) {
            float gA = S->gate[e0 + mt * 16 + r];
            float gB = S->gate[e0 + mt * 16 + 8 + r];
#pragma unroll
            for (int nt = 0; nt < 4; nt++) {
                int c = c0 + nt * 8 + n2;
                float b0v = bias[c], b1v = bias[c + 1];
                mc[nt][0] += gA * siluf(acc[mt][nt][0] + b0v)
                           + gB * siluf(acc[mt][nt][2] + b0v);
                mc[nt][1] += gA * siluf(acc[mt][nt][1] + b1v)
                           + gB * siluf(acc[mt][nt][3] + b1v);
            }
        }
#pragma unroll
        for (int nt = 0; nt < 4; nt++)
#pragma unroll
            for (int j = 0; j < 2; j++) {
                float v = mc[nt][j];
                v += __shfl_xor_sync(0xffffffffu, v, 4);
                v += __shfl_xor_sync(0xffffffffu, v, 8);
                v += __shfl_xor_sync(0xffffffffu, v, 16);
                mc[nt][j] = v;
            }
        if (lane < 4) {
            int eg = w >> 2;
#pragma unroll
            for (int nt = 0; nt < 4; nt++)
#pragma unroll
                for (int j = 0; j < 2; j++) {
                    int c = c0 + nt * 8 + lane * 2 + j;
                    S->maggs[eg * FD + c] += mc[nt][j];
                }
        }
    }
}

__global__ void __launch_bounds__(NTHR, 2)
kedge(const int* __restrict__ senders, const float* __restrict__ We0r0,
      const float* __restrict__ be1, const float* __restrict__ bx1,
      const float* __restrict__ Wxo, const float* __restrict__ bxop,
      const float* __restrict__ We2g, const float* __restrict__ be2g, int blk)
{
    extern __shared__ char smraw[];
    ES* S = reinterpret_cast<ES*>(smraw);
    const int t = threadIdx.x, i = blockIdx.x;
    const int w = t >> 5, lane = t & 31;
    const int g = w & 3;
    const int pl = ((w >> 2) << 5) | lane;
    const __nv_bfloat16* wb = g_wb + blk * 3 * 32768;
    const float* aux = g_aux + blk * 257;

    if (t < FD) {
        S->w0[t] = We0r0[t]; S->hrb[t] = g_hr[i * FD + t];
        S->winf[t] = aux[t];            // we2winf
        S->bb2[t] = aux[FD + t];        // bc
        S->wxo[t] = Wxo[t];
        S->bb1[t] = be1[t]; S->bbx1[t] = bx1[t];
    }
    S->maggs[t] = 0.f;
    if (t < 4) S->vaccs[t] = 0.f;
    if (t < 3) S->rvec[t] = g_vec[i * 3 + t];
    const float binf_s = aux[256], bxo_s = bxop[0];

    loadBpair(S->bbuf + g * 8192, wb + g * 4096, pl);   // We1 hi, pair region
    __syncthreads();

    for (int tile = 0; tile < NTILE; tile++) {
        if (t < TILE) {                                  // stage 1
            int je = tile * TILE + t;
            bool valid = je < EPN;
            int s = valid ? senders[i * EPN + je] : i;
            S->sidx[t] = s;
            float d0 = 0.f, d1 = 0.f, d2 = 0.f;
            if (valid) {
                d0 = S->rvec[0] - g_vec[s * 3 + 0];
                d1 = S->rvec[1] - g_vec[s * 3 + 1];
                d2 = S->rvec[2] - g_vec[s * 3 + 2];
            }
            S->dv[t * 3] = d0; S->dv[t * 3 + 1] = d1; S->dv[t * 3 + 2] = d2;
            float dot = d0 * d0 + d1 * d1 + d2 * d2 + 1e-20f;
            S->l2[t] = valid ? dot : 0.f;
            S->len[t] = sqrtf(dot);
        }
        __syncthreads();
        {                                                // stage 2: act0 -> X
            int e = t >> 2, kh = t & 3;
            int s = S->sidx[e];
            float l2v = S->l2[e];
            const float* hsr = g_hs + s * FD + kh * 32;
#pragma unroll 8
            for (int j = 0; j < 32; j += 2) {
                int c = kh * 32 + j;
                float v0 = siluf(l2v * S->w0[c]     + hsr[j]     + S->hrb[c]);
                float v1 = siluf(l2v * S->w0[c + 1] + hsr[j + 1] + S->hrb[c + 1]);
                st_split2(S->xhi, S->xlo, img_off(e, c), v0, v1);
            }
        }
        __syncthreads();

        // G1: Y = silu(X @ We1 + be1); gate dot (we2winf) + ys/gs fold
        gemm_tc<true, true, true, true>(S, S->xhi, S->xlo,
                                   wb + 0 * 32768, wb + 1 * 32768,
                                   S->bb1, S->winf, S->yhi, S->ylo, t,
                                   binf_s, tile);
        __syncthreads();

        // G3': Y2 = silu(Y @ Wc + bc)   (Wc = We2@Wx0 precomputed)
        gemm_tc<true, false, true>(S, S->yhi, S->ylo,
                                   wb + 1 * 32768, wb + 2 * 32768,
                                   S->bb2, 0, S->xhi, S->xlo, t);
        __syncthreads();

        // G4: px partial = silu(Y2 @ Wx1 + bx1) . wxo  (no store); next = We1
        gemm_tc<true, true, false>(S, S->xhi, S->xlo,
                                   wb + 2 * 32768, wb + 0 * 32768,
                                   S->bbx1, S->wxo, S->yhi, S->ylo, t);
        __syncthreads();
        if (t < TILE) {                                  // px + vac products
            float p = __fdividef(bxo_s + S->gpart[t] + S->gpart[TILE + t]
                                 + S->gpart[2 * TILE + t] + S->gpart[3 * TILE + t],
                                 1.f + S->len[t]);
            S->vred[t] = p * S->dv[t * 3];
            S->vred[TILE + t] = p * S->dv[t * 3 + 1];
            S->vred[2 * TILE + t] = p * S->dv[t * 3 + 2];
        }
        __syncthreads();
        if (t < 96) {
            int c = t >> 5, l = t & 31;
            const float* vr = S->vred + c * TILE;
            float v = vr[l] + vr[l + 32];
#pragma unroll
            for (int o = 16; o; o >>= 1) v += __shfl_down_sync(0xffffffffu, v, o);
            if (l == 0) S->vaccs[c] += v;
        }
        __syncthreads();
    }

    // writeout: magg = (ys @ We2) + gs*be2, scaled
    if (t < FD) S->gpart[t] = S->maggs[t] + S->maggs[FD + t];   // ys
    __syncthreads();
    if (t < FD) {
        float a = S->vaccs[3] * be2g[t];
#pragma unroll 8
        for (int k = 0; k < FD; k++) a += S->gpart[k] * We2g[k * FD + t];
        g_magg[i * FD + t] = a * rsqrtf(511.f);
    }
    if (t < 3) g_vac[i * 3 + t] = S->vaccs[t] * (1.f / 511.f);
}

// weights -> T[n][k] bf16 hi/lo swizzled images.
// grid 6: m = b*3+g; g0: We1 copy, g1: Wc = We2@Wx0 (smem-staged matmul) + aux,
// g2: Wx1 copy
__global__ void __launch_bounds__(256) kwprep(
    const float* __restrict__ We1, const float* __restrict__ We2,
    const float* __restrict__ Wx0, const float* __restrict__ Wx1,
    const float* __restrict__ Winf, const float* __restrict__ be2,
    const float* __restrict__ bx0, const float* __restrict__ binf)
{
    extern __shared__ float sW[];          // 128KB: [Wx0 | We2] fp32
    int m = blockIdx.x, b = m / 3, g = m % 3;
    int t = threadIdx.x;
    char* blob = reinterpret_cast<char*>(g_wb + m * 32768);

    if (g == 1) {
        const float* We2g = We2 + b * FD * FD;
        const float* Wx0g = Wx0 + b * FD * FD;
        const float* winfg = Winf + b * FD;
        const float* be2g = be2 + b * FD;
        const float* bx0g = bx0 + b * FD;
        float* sA = sW;                  // Wx0
        float* sB = sW + FD * FD;        // We2
        float* aux = g_aux + b * 257;
        for (int idx = t; idx < FD * FD; idx += 256) {
            sA[idx] = Wx0g[idx];
            sB[idx] = We2g[idx];
        }
        __syncthreads();
        for (int ii = 0; ii < 64; ii++) {
            int idx = t + ii * 256;
            int k = idx >> 7, n = idx & 127;
            const float* br = sB + k * FD;
            float a0 = 0.f, a1 = 0.f, a2 = 0.f, a3 = 0.f;
#pragma unroll 8
            for (int j = 0; j < FD; j += 4) {
                a0 += br[j]     * sA[j * FD + n];
                a1 += br[j + 1] * sA[(j + 1) * FD + n];
                a2 += br[j + 2] * sA[(j + 2) * FD + n];
                a3 += br[j + 3] * sA[(j + 3) * FD + n];
            }
            float a = (a0 + a1) + (a2 + a3);
            __nv_bfloat16 h = __float2bfloat16(a);
            __nv_bfloat16 l = __float2bfloat16(a - __bfloat162float(h));
            int off = (n << 8) + ((((k >> 3) ^ (n & 7))) << 4) + ((k & 7) << 1);
            *reinterpret_cast<__nv_bfloat16*>(blob + off) = h;
            *reinterpret_cast<__nv_bfloat16*>(blob + 32768 + off) = l;
        }
        if (t < FD) {
            float a = 0.f;
#pragma unroll 8
            for (int c = 0; c < FD; c++) a += sB[t * FD + c] * winfg[c];
            aux[t] = a;                       // we2winf
            float bcv = bx0g[t];
#pragma unroll 8
            for (int j = 0; j < FD; j++) bcv += be2g[j] * sA[j * FD + t];
            aux[FD + t] = bcv;                // bc
        }
        if (t == 0) {
            float a = binf[b];
#pragma unroll 8
            for (int c = 0; c < FD; c++) a += be2g[c] * winfg[c];
            aux[256] = a;                     // binf'
        }
        return;
    }

    const float* W = (g == 0 ? We1 : Wx1) + b * FD * FD;
    int n = t & 127, kh = t >> 7;
    for (int kc = 0; kc < 8; kc++) {
        int kchunk = kh * 8 + kc;
        unsigned qh[4], ql[4];
#pragma unroll
        for (int u = 0; u < 4; u++) {
            int k = kchunk * 8 + u * 2;
            float x0 = W[k * FD + n], x1 = W[(k + 1) * FD + n];
            __nv_bfloat16 h0 = __float2bfloat16(x0), h1 = __float2bfloat16(x1);
            __nv_bfloat16 l0 = __float2bfloat16(x0 - __bfloat162float(h0));
            __nv_bfloat16 l1 = __float2bfloat16(x1 - __bfloat162float(h1));
            qh[u] = (unsigned)__bfloat16_as_ushort(h0) | ((unsigned)__bfloat16_as_ushort(h1) << 16);
            ql[u] = (unsigned)__bfloat16_as_ushort(l0) | ((unsigned)__bfloat16_as_ushort(l1) << 16);
        }
        int off = (n << 8) + ((kchunk ^ (n & 7)) << 4);
        *reinterpret_cast<uint4*>(blob + off)         = make_uint4(qh[0], qh[1], qh[2], qh[3]);
        *reinterpret_cast<uint4*>(blob + 32768 + off) = make_uint4(ql[0], ql[1], ql[2], ql[3]);
    }
}

__global__ void ksetup(const float* __restrict__ x)
{
    __shared__ float r0[256], r1[256], r2[256];
    __shared__ float mean[3];
    int t = threadIdx.x;
    float s0 = 0.f, s1 = 0.f, s2 = 0.f;
    for (int n = t; n < NN; n += 256) {
        s0 += x[n * 3]; s1 += x[n * 3 + 1]; s2 += x[n * 3 + 2];
    }
    r0[t] = s0; r1[t] = s1; r2[t] = s2;
    __syncthreads();
    for (int s = 128; s > 0; s >>= 1) {
        if (t < s) { r0[t] += r0[t + s]; r1[t] += r1[t + s]; r2[t] += r2[t + s]; }
        __syncthreads();
    }
    if (t == 0) { mean[0] = r0[0] / NN; mean[1] = r1[0] / NN; mean[2] = r2[0] / NN; }
    __syncthreads();
    for (int n = t; n < NN; n += 256)
#pragma unroll
        for (int c = 0; c < 3; c++) {
            float v = x[n * 3 + c] - mean[c];
            g_vec[n * 3 + c] = v; g_vec0[n * 3 + c] = v;
        }
}

__global__ void __launch_bounds__(256) knode0(
    const float* __restrict__ h,
    const float* __restrict__ Wh0, const float* __restrict__ bh0,
    const float* __restrict__ We0, const float* __restrict__ be0)
{
    __shared__ float hrow[16];
    __shared__ float hfs[FD];
    __shared__ float part[256];
    int i = blockIdx.x, t = threadIdx.x;
    int c = t & 127, hh = t >> 7;
    if (t < 16) hrow[t] = h[i * 16 + t];
    __syncthreads();
    if (t < FD) {
        float acc = bh0[t];
#pragma unroll
        for (int k = 0; k < 16; k++) acc += hrow[k] * Wh0[k * FD + t];
        g_hf[i * FD + t] = acc;
        hfs[t] = acc;
    }
    __syncthreads();
    {
        float a0 = 0.f, a1 = 0.f, b0 = 0.f, b1 = 0.f;
        const float* W1 = We0 + (1 + hh * 64) * FD;
        const float* W2 = We0 + (129 + hh * 64) * FD;
        const float* xv = hfs + hh * 64;
#pragma unroll 4
        for (int k = 0; k < 64; k += 2) {
            a0 += xv[k] * W1[k * FD + c];       a1 += xv[k + 1] * W1[(k + 1) * FD + c];
            b0 += xv[k] * W2[k * FD + c];       b1 += xv[k + 1] * W2[(k + 1) * FD + c];
        }
        part[t] = a0 + a1;
        __syncthreads();
        if (t < FD) g_hs[i * FD + t] = part[t] + part[t + FD];
        __syncthreads();
        part[t] = b0 + b1;
        __syncthreads();
        if (t < FD) g_hr[i * FD + t] = part[t] + part[t + FD] + be0[t];
    }
}

__global__ void __launch_bounds__(256) knode(
    const float* __restrict__ Wp0, const float* __restrict__ bp0,
    const float* __restrict__ Wp1, const float* __restrict__ bp1,
    const float* __restrict__ Wpl, const float* __restrict__ bpl,
    const float* __restrict__ We0n, const float* __restrict__ be0n,
    int doNext)
{
    __shared__ float in0[2 * FD];
    __shared__ float t0s[FD];
    __shared__ float t1s[FD];
    __shared__ float nhfs[FD];
    __shared__ float part[256];
    int i = blockIdx.x, t = threadIdx.x;
    int c = t & 127, hh = t >> 7;

    if (t < 3) g_vec[i * 3 + t] += g_vac[i * 3 + t];
    if (t < FD) in0[t] = g_magg[i * FD + t];
    else        in0[t] = g_hf[i * FD + (t - FD)];
    __syncthreads();

    // Wp0: 256 x 128, split k over two halves
    {
        float a0 = 0.f, a1 = 0.f, a2 = 0.f, a3 = 0.f;
        const float* W  = Wp0 + hh * FD * FD;
        const float* xv = in0 + hh * FD;
#pragma unroll 4
        for (int k = 0; k < FD; k += 4) {
            a0 += xv[k]     * W[(k    ) * FD + c];
            a1 += xv[k + 1] * W[(k + 1) * FD + c];
            a2 += xv[k + 2] * W[(k + 2) * FD + c];
            a3 += xv[k + 3] * W[(k + 3) * FD + c];
        }
        part[t] = (a0 + a1) + (a2 + a3);
    }
    __syncthreads();
    if (t < FD) t0s[t] = siluf(part[t] + part[t + FD] + bp0[t]);
    __syncthreads();

    // Wp1: 128 x 128
    {
        float a0 = 0.f, a1 = 0.f, a2 = 0.f, a3 = 0.f;
        const float* W  = Wp1 + hh * 64 * FD;
        const float* xv = t0s + hh * 64;
#pragma unroll 4
        for (int k = 0; k < 64; k += 4) {
            a0 += xv[k]     * W[(k    ) * FD + c];
            a1 += xv[k + 1] * W[(k + 1) * FD + c];
            a2 += xv[k + 2] * W[(k + 2) * FD + c];
            a3 += xv[k + 3] * W[(k + 3) * FD + c];
        }
        part[t] = (a0 + a1) + (a2 + a3);
    }
    __syncthreads();
    if (t < FD) t1s[t] = part[t] + part[t + FD] + bp1[t];
    __syncthreads();

    // Wpl: 128 x 128
    {
        float a0 = 0.f, a1 = 0.f, a2 = 0.f, a3 = 0.f;
        const float* W  = Wpl + hh * 64 * FD;
        const float* xv = t1s + hh * 64;
#pragma unroll 4
        for (int k = 0; k < 64; k += 4) {
            a0 += xv[k]     * W[(k    ) * FD + c];
            a1 += xv[k + 1] * W[(k + 1) * FD + c];
            a2 += xv[k + 2] * W[(k + 2) * FD + c];
            a3 += xv[k + 3] * W[(k + 3) * FD + c];
        }
        part[t] = (a0 + a1) + (a2 + a3);
    }
    __syncthreads();
    if (t < FD) {
        float nhf = g_hf[i * FD + t] + part[t] + part[t + FD] + bpl[t];
        g_hf[i * FD + t] = nhf;
        nhfs[t] = nhf;
    }
    __syncthreads();

    if (doNext) {
        float a0 = 0.f, a1 = 0.f, b0 = 0.f, b1 = 0.f;
        const float* W1 = We0n + (1 + hh * 64) * FD;
        const float* W2 = We0n + (129 + hh * 64) * FD;
        const float* xv = nhfs + hh * 64;
#pragma unroll 4
        for (int k = 0; k < 64; k += 2) {
            a0 += xv[k] * W1[k * FD + c];       a1 += xv[k + 1] * W1[(k + 1) * FD + c];
            b0 += xv[k] * W2[k * FD + c];       b1 += xv[k + 1] * W2[(k + 1) * FD + c];
        }
        part[t] = a0 + a1;
        __syncthreads();
        if (t < FD) g_hs[i * FD + t] = part[t] + part[t + FD];
        __syncthreads();
        part[t] = b0 + b1;
        __syncthreads();
        if (t < FD) g_hr[i * FD + t] = part[t] + part[t + FD] + be0n[t];
    }
}

__global__ void kout(const float* __restrict__ Wv,
                     const float* __restrict__ Wr, const float* __restrict__ br,
                     float* __restrict__ out)
{
    __shared__ float red[FD], p[FD];
    int i = blockIdx.x, c = threadIdx.x;
    float hf = g_hf[i * FD + c];
    red[c] = hf;
    __syncthreads();
    for (int s = 64; s > 0; s >>= 1) {
        if (c < s) red[c] = fmaxf(red[c], red[c + s]);
        __syncthreads();
    }
    float mx = red[0];
    __syncthreads();
    float ex = __expf(hf - mx);
    red[c] = ex;
    __syncthreads();
    for (int s = 64; s > 0; s >>= 1) {
        if (c < s) red[c] += red[c + s];
        __syncthreads();
    }
    float inv = 1.f / red[0];
    __syncthreads();
    p[c] = ex * inv;
    __syncthreads();
    if (c < 32) {
        float a = br[c];
#pragma unroll 8
        for (int k = 0; k < FD; k++) a += p[k] * Wr[k * 32 + c];
        out[NN * 6 + i * 32 + c] = a;
    }
    if (c < 6) {
        int o = c / 3, cc = c % 3;
        out[i * 6 + c] = (g_vec[i * 3 + cc] - g_vec0[i * 3 + cc]) * Wv[o];
    }
}

extern "C" void kernel_launch(void* const* d_in, const int* in_sizes, int n_in,
                              void* d_out, int out_size)
{
    const float* x   = (const float*)d_in[0];
    const float* h   = (const float*)d_in[1];
    const int* snd   = (const int*)  d_in[2];
    const float* Wh0 = (const float*)d_in[4];
    const float* bh0 = (const float*)d_in[5];
    const float* We0 = (const float*)d_in[6];
    const float* be0 = (const float*)d_in[7];
    const float* We1 = (const float*)d_in[8];
    const float* be1 = (const float*)d_in[9];
    const float* We2 = (const float*)d_in[10];
    const float* be2 = (const float*)d_in[11];
    const float* Winf= (const float*)d_in[12];
    const float* binf= (const float*)d_in[13];
    const float* Wx0 = (const float*)d_in[14];
    const float* bx0 = (const float*)d_in[15];
    const float* Wx1 = (const float*)d_in[16];
    const float* bx1 = (const float*)d_in[17];
    const float* Wxo = (const float*)d_in[18];
    const float* bxo = (const float*)d_in[19];
    const float* Wp0 = (const float*)d_in[20];
    const float* bp0 = (const float*)d_in[21];
    const float* Wp1 = (const float*)d_in[22];
    const float* bp1 = (const float*)d_in[23];
    const float* Wpl = (const float*)d_in[24];
    const float* bpl = (const float*)d_in[25];
    const float* Wv  = (const float*)d_in[26];
    const float* Wr  = (const float*)d_in[27];
    const float* br  = (const float*)d_in[28];
    float* out = (float*)d_out;

    int smem = (int)sizeof(ES);
    cudaFuncSetAttribute(kedge, cudaFuncAttributeMaxDynamicSharedMemorySize, smem);
    cudaFuncSetAttribute(kwprep, cudaFuncAttributeMaxDynamicSharedMemorySize, 131072);

    const int WB = FD * FD, W0B = 257 * FD, WP0 = 2 * FD * FD;

    ksetup<<<1, 256>>>(x);
    knode0<<<NN, 256>>>(h, Wh0, bh0, We0, be0);
    kwprep<<<6, 256, 131072>>>(We1, We2, Wx0, Wx1, Winf, be2, bx0, binf);

    for (int b = 0; b < 2; b++) {
        kedge<<<NN, NTHR, smem>>>(snd, We0 + b * W0B,
            be1 + b * FD, bx1 + b * FD, Wxo + b * FD, bxo + b,
            We2 + b * WB, be2 + b * FD, b);
        knode<<<NN, 256>>>(Wp0 + b * WP0, bp0 + b * FD,
                           Wp1 + b * WB, bp1 + b * FD,
                           Wpl + b * WB, bpl + b * FD,
                           We0 + W0B, be0 + FD, b == 0 ? 1 : 0);
    }
    kout<<<NN, FD>>>(Wv, Wr, br, out);
}